// round 1
// baseline (speedup 1.0000x reference)
#include <cuda_runtime.h>
#include <cstdint>

// ---------------------------------------------------------------------------
// Problem constants (B=16, 56x56x384, 12 heads, 7x7 windows, shift 3)
// ---------------------------------------------------------------------------
constexpr int Bq    = 16;
constexpr int IMG   = 56;
constexpr int C     = 384;
constexpr int NH    = 12;
constexpr int HD    = 32;
constexpr int WS    = 7;     // window size
constexpr int SHF   = 3;     // shift
constexpr int NWIN1 = 8;     // windows per axis (56/7)
constexpr int NWIN  = NWIN1 * NWIN1;        // 64 windows / image
constexpr int NT    = WS * WS;              // 49 tokens / window
constexpr int NWTOT = Bq * NWIN;            // 1024 windows total
constexpr int MROWS = NWTOT * NT;           // 50176
constexpr int NQKV  = 3 * C;                // 1152

// Scratch (device globals; no runtime allocation allowed)
__device__ float g_qkv[(size_t)MROWS * NQKV];   // [m, 1152]
__device__ float g_att[(size_t)MROWS * C];      // [m, 384]

// ---------------------------------------------------------------------------
// row m (window-token index) -> byte-element offset into the [16,56,56,384]
// image, applying the shifted-window gather (roll by -3 == read (p+3)%56).
// The inverse scatter (roll +3 after merge) is the SAME mapping, so this
// serves both the QKV gather and the proj epilogue scatter.
// ---------------------------------------------------------------------------
__device__ __forceinline__ int row_img_offset(int m) {
    int wwin = m / NT;              // 0..1023
    int t    = m - wwin * NT;       // 0..48
    int b  = wwin >> 6;             // /64
    int wi = wwin & 63;
    int iw = wi >> 3, jw = wi & 7;
    int r  = t / WS, c = t - r * WS;
    int ph = iw * WS + r;
    int pw = jw * WS + c;
    int h = ph + SHF; if (h >= IMG) h -= IMG;
    int w = pw + SHF; if (w >= IMG) w -= IMG;
    return ((b * IMG + h) * IMG + w) * C;
}

// ---------------------------------------------------------------------------
// SGEMM: 128x128 tile, BK=8, 256 threads, 8x8 microtile.
// Kernel 1: gathered A (from image) @ qkv_weight^T + bias -> g_qkv
// ---------------------------------------------------------------------------
__global__ __launch_bounds__(256) void qkv_gemm(const float* __restrict__ x,
                                                const float* __restrict__ Wt,     // [1152,384]
                                                const float* __restrict__ bias) { // [1152]
    __shared__ float As[8][128];
    __shared__ float Bs[8][128];
    __shared__ int   rowOff[128];

    const int tid = threadIdx.x;
    const int m0 = blockIdx.y * 128;
    const int n0 = blockIdx.x * 128;

    if (tid < 128) rowOff[tid] = row_img_offset(m0 + tid);

    const int tx = tid & 15;        // n direction
    const int ty = tid >> 4;        // m direction
    const int lr = tid >> 1;        // load row 0..127
    const int lk = (tid & 1) * 4;   // k sub-offset

    float acc[8][8];
    #pragma unroll
    for (int i = 0; i < 8; i++)
        #pragma unroll
        for (int j = 0; j < 8; j++) acc[i][j] = 0.f;

    __syncthreads();  // rowOff ready

    const float* bRow = Wt + (size_t)(n0 + lr) * C;

    for (int k0 = 0; k0 < C; k0 += 8) {
        float4 a4 = *(const float4*)(x + rowOff[lr] + k0 + lk);
        float4 b4 = *(const float4*)(bRow + k0 + lk);
        __syncthreads();
        As[lk + 0][lr] = a4.x; As[lk + 1][lr] = a4.y;
        As[lk + 2][lr] = a4.z; As[lk + 3][lr] = a4.w;
        Bs[lk + 0][lr] = b4.x; Bs[lk + 1][lr] = b4.y;
        Bs[lk + 2][lr] = b4.z; Bs[lk + 3][lr] = b4.w;
        __syncthreads();
        #pragma unroll
        for (int kk = 0; kk < 8; kk++) {
            float a[8], b[8];
            #pragma unroll
            for (int i = 0; i < 8; i++) a[i] = As[kk][ty * 8 + i];
            #pragma unroll
            for (int j = 0; j < 8; j++) b[j] = Bs[kk][tx * 8 + j];
            #pragma unroll
            for (int i = 0; i < 8; i++)
                #pragma unroll
                for (int j = 0; j < 8; j++) acc[i][j] += a[i] * b[j];
        }
    }

    #pragma unroll
    for (int i = 0; i < 8; i++) {
        int m = m0 + ty * 8 + i;
        float* dst = g_qkv + (size_t)m * NQKV + n0 + tx * 8;
        #pragma unroll
        for (int j = 0; j < 8; j++) dst[j] = acc[i][j] + bias[n0 + tx * 8 + j];
    }
}

// ---------------------------------------------------------------------------
// Kernel 3: proj GEMM + scatter back through the inverse window/roll mapping.
// ---------------------------------------------------------------------------
__global__ __launch_bounds__(256) void proj_gemm(const float* __restrict__ Wt,     // [384,384]
                                                 const float* __restrict__ bias,   // [384]
                                                 float* __restrict__ out) {
    __shared__ float As[8][128];
    __shared__ float Bs[8][128];
    __shared__ int   rowOff[128];

    const int tid = threadIdx.x;
    const int m0 = blockIdx.y * 128;
    const int n0 = blockIdx.x * 128;

    if (tid < 128) rowOff[tid] = row_img_offset(m0 + tid);

    const int tx = tid & 15;
    const int ty = tid >> 4;
    const int lr = tid >> 1;
    const int lk = (tid & 1) * 4;

    float acc[8][8];
    #pragma unroll
    for (int i = 0; i < 8; i++)
        #pragma unroll
        for (int j = 0; j < 8; j++) acc[i][j] = 0.f;

    __syncthreads();

    const float* aRow = g_att + (size_t)(m0 + lr) * C;
    const float* bRow = Wt + (size_t)(n0 + lr) * C;

    for (int k0 = 0; k0 < C; k0 += 8) {
        float4 a4 = *(const float4*)(aRow + k0 + lk);
        float4 b4 = *(const float4*)(bRow + k0 + lk);
        __syncthreads();
        As[lk + 0][lr] = a4.x; As[lk + 1][lr] = a4.y;
        As[lk + 2][lr] = a4.z; As[lk + 3][lr] = a4.w;
        Bs[lk + 0][lr] = b4.x; Bs[lk + 1][lr] = b4.y;
        Bs[lk + 2][lr] = b4.z; Bs[lk + 3][lr] = b4.w;
        __syncthreads();
        #pragma unroll
        for (int kk = 0; kk < 8; kk++) {
            float a[8], b[8];
            #pragma unroll
            for (int i = 0; i < 8; i++) a[i] = As[kk][ty * 8 + i];
            #pragma unroll
            for (int j = 0; j < 8; j++) b[j] = Bs[kk][tx * 8 + j];
            #pragma unroll
            for (int i = 0; i < 8; i++)
                #pragma unroll
                for (int j = 0; j < 8; j++) acc[i][j] += a[i] * b[j];
        }
    }

    #pragma unroll
    for (int i = 0; i < 8; i++) {
        float* dst = out + rowOff[ty * 8 + i] + n0 + tx * 8;
        #pragma unroll
        for (int j = 0; j < 8; j++) dst[j] = acc[i][j] + bias[n0 + tx * 8 + j];
    }
}

// ---------------------------------------------------------------------------
// Kernel 2: per (window, head) attention. 49 tokens, hd=32.
// Reads q,k,v slices from g_qkv, adds rel-pos bias + shifted-window mask
// (both computed inline), softmax, P@V -> g_att.
// ---------------------------------------------------------------------------
__global__ __launch_bounds__(128) void attn_kernel(const float* __restrict__ table) { // [169,12]
    const int h    = blockIdx.x;   // head 0..11
    const int wwin = blockIdx.y;   // window 0..1023

    __shared__ float qs[NT * HD];
    __shared__ float ks[NT * HD];
    __shared__ float vs[NT * HD];
    __shared__ float s[NT][52];
    __shared__ float biasTab[169];
    __shared__ int   cnt[NT];

    const int tid = threadIdx.x;
    const float scale = 0.17677669529663687f;  // 32^-0.5

    // load q/k/v slices for this head
    for (int e = tid; e < NT * HD; e += 128) {
        int i = e >> 5, d = e & 31;
        const float* row = g_qkv + (size_t)(wwin * NT + i) * NQKV + h * HD + d;
        qs[e] = row[0] * scale;
        ks[e] = row[C];
        vs[e] = row[2 * C];
    }
    for (int e = tid; e < 169; e += 128) biasTab[e] = table[e * NH + h];

    // shifted-window mask region ids (nontrivial only for last row/col windows)
    const int wi = wwin & 63;
    const int iw = wi >> 3, jw = wi & 7;
    if (tid < NT) {
        int r = tid / WS, c = tid - (tid / WS) * WS;
        int ch = (iw < NWIN1 - 1) ? 0 : (r < WS - SHF ? 1 : 2);
        int cw = (jw < NWIN1 - 1) ? 0 : (c < WS - SHF ? 1 : 2);
        cnt[tid] = ch * 3 + cw;
    }
    __syncthreads();

    // scores
    for (int p = tid; p < NT * NT; p += 128) {
        int i = p / NT, j = p - i * NT;
        float acc = 0.f;
        #pragma unroll
        for (int d = 0; d < HD; d++) acc += qs[i * HD + d] * ks[j * HD + d];
        int r1 = i / WS, c1 = i - r1 * WS;
        int r2 = j / WS, c2 = j - r2 * WS;
        acc += biasTab[(r1 - r2 + WS - 1) * (2 * WS - 1) + (c1 - c2 + WS - 1)];
        if (cnt[i] != cnt[j]) acc -= 100.f;
        s[i][j] = acc;
    }
    __syncthreads();

    // softmax (one thread per row; 49 rows)
    if (tid < NT) {
        float mx = -1e30f;
        #pragma unroll 7
        for (int j = 0; j < NT; j++) mx = fmaxf(mx, s[tid][j]);
        float sum = 0.f;
        #pragma unroll 7
        for (int j = 0; j < NT; j++) { float e = __expf(s[tid][j] - mx); s[tid][j] = e; sum += e; }
        float inv = 1.f / sum;
        #pragma unroll 7
        for (int j = 0; j < NT; j++) s[tid][j] *= inv;
    }
    __syncthreads();

    // P @ V
    for (int o = tid; o < NT * HD; o += 128) {
        int i = o >> 5, d = o & 31;
        float acc = 0.f;
        #pragma unroll 7
        for (int j = 0; j < NT; j++) acc += s[i][j] * vs[j * HD + d];
        g_att[(size_t)(wwin * NT + i) * C + h * HD + d] = acc;
    }
}

// ---------------------------------------------------------------------------
extern "C" void kernel_launch(void* const* d_in, const int* in_sizes, int n_in,
                              void* d_out, int out_size) {
    const float* x     = (const float*)d_in[0];
    const float* qkvw  = (const float*)d_in[1];
    const float* qkvb  = (const float*)d_in[2];
    const float* projw = (const float*)d_in[3];
    const float* projb = (const float*)d_in[4];
    const float* table = (const float*)d_in[5];
    float* out = (float*)d_out;

    dim3 gQ(NQKV / 128, MROWS / 128);   // (9, 392)
    qkv_gemm<<<gQ, 256>>>(x, qkvw, qkvb);

    attn_kernel<<<dim3(NH, NWTOT), 128>>>(table);

    dim3 gP(C / 128, MROWS / 128);      // (3, 392)
    proj_gemm<<<gP, 256>>>(projw, projb, out);
}

// round 3
// speedup vs baseline: 2.0903x; 2.0903x over previous
#include <cuda_runtime.h>
#include <cuda_bf16.h>
#include <cstdint>

// ---------------------------------------------------------------------------
// Problem constants (B=16, 56x56x384, 12 heads, 7x7 windows, shift 3)
// ---------------------------------------------------------------------------
constexpr int IMG   = 56;
constexpr int C     = 384;
constexpr int NH    = 12;
constexpr int HD    = 32;
constexpr int WS    = 7;
constexpr int SHF   = 3;
constexpr int NWIN1 = 8;
constexpr int NT    = WS * WS;            // 49
constexpr int NWTOT = 16 * 64;            // 1024 windows
constexpr int MROWS = 16 * IMG * IMG;     // 50176 pixels == window tokens
constexpr int NQKV  = 3 * C;              // 1152

// ---------------------------------------------------------------------------
// Device-global scratch (no runtime allocation allowed)
// ---------------------------------------------------------------------------
__device__ float          g_qkv[(size_t)MROWS * NQKV];       // pixel-order qkv
__device__ __nv_bfloat16  g_xhi[(size_t)MROWS * C];
__device__ __nv_bfloat16  g_xlo[(size_t)MROWS * C];
__device__ __nv_bfloat16  g_ahi[(size_t)MROWS * C];          // attention out hi
__device__ __nv_bfloat16  g_alo[(size_t)MROWS * C];          // attention out lo
__device__ __nv_bfloat16  g_wqh[(size_t)NQKV * C];
__device__ __nv_bfloat16  g_wql[(size_t)NQKV * C];
__device__ __nv_bfloat16  g_wph[(size_t)C * C];
__device__ __nv_bfloat16  g_wpl[(size_t)C * C];

// ---------------------------------------------------------------------------
// Warp-MMA helpers (portable: sm_80+ PTX, no 'a' features)
// ---------------------------------------------------------------------------
__device__ __forceinline__ uint32_t smem_u32(const void* p) {
    uint32_t a;
    asm("{ .reg .u64 t; cvta.to.shared.u64 t, %1; cvt.u32.u64 %0, t; }"
        : "=r"(a) : "l"(p));
    return a;
}

__device__ __forceinline__ void ldsm_x4(uint32_t& r0, uint32_t& r1,
                                        uint32_t& r2, uint32_t& r3, uint32_t addr) {
    asm volatile("ldmatrix.sync.aligned.m8n8.x4.shared.b16 {%0,%1,%2,%3}, [%4];"
                 : "=r"(r0), "=r"(r1), "=r"(r2), "=r"(r3) : "r"(addr));
}

__device__ __forceinline__ void mma16816(float* d, const uint32_t* a, const uint32_t* b) {
    asm volatile(
        "mma.sync.aligned.m16n8k16.row.col.f32.bf16.bf16.f32 "
        "{%0,%1,%2,%3}, {%4,%5,%6,%7}, {%8,%9}, {%0,%1,%2,%3};"
        : "+f"(d[0]), "+f"(d[1]), "+f"(d[2]), "+f"(d[3])
        : "r"(a[0]), "r"(a[1]), "r"(a[2]), "r"(a[3]), "r"(b[0]), "r"(b[1]));
}

// SW128 swizzle on byte offsets within a tile of 128B rows
__device__ __forceinline__ uint32_t sw128(uint32_t o) { return o ^ ((o >> 3) & 0x70); }

// ---------------------------------------------------------------------------
// fp32 -> bf16 hi/lo split (x = hi + lo)
// ---------------------------------------------------------------------------
__global__ void conv_split4(const float4* __restrict__ src,
                            __nv_bfloat16* __restrict__ hi,
                            __nv_bfloat16* __restrict__ lo, int n4) {
    int i = blockIdx.x * blockDim.x + threadIdx.x;
    if (i >= n4) return;
    float4 v = src[i];
    float vv[4] = {v.x, v.y, v.z, v.w};
    __nv_bfloat16 h[4], l[4];
#pragma unroll
    for (int j = 0; j < 4; j++) {
        h[j] = __float2bfloat16(vv[j]);
        l[j] = __float2bfloat16(vv[j] - __bfloat162float(h[j]));
    }
    __nv_bfloat162* hp = (__nv_bfloat162*)(hi + (size_t)i * 4);
    __nv_bfloat162* lp = (__nv_bfloat162*)(lo + (size_t)i * 4);
    hp[0] = __nv_bfloat162(h[0], h[1]); hp[1] = __nv_bfloat162(h[2], h[3]);
    lp[0] = __nv_bfloat162(l[0], l[1]); lp[1] = __nv_bfloat162(l[2], l[3]);
}

// ---------------------------------------------------------------------------
// HMMA GEMM: out[M,N] = (Ahi+Alo)[M,384] @ (Bhi+Blo)[N,384]^T + bias
// 3 passes (hi*hi, hi*lo, lo*hi). CTA tile 128x128, BK=64, 8 warps,
// warp tile 64x32 via m16n8k16. grid=(M/128, N/128), 256 threads.
// ---------------------------------------------------------------------------
__global__ __launch_bounds__(256) void mma_gemm(
    const __nv_bfloat16* __restrict__ Ahi, const __nv_bfloat16* __restrict__ Alo,
    const __nv_bfloat16* __restrict__ Bhi, const __nv_bfloat16* __restrict__ Blo,
    const float* __restrict__ bias, float* __restrict__ out, int ldout) {

    __shared__ __align__(1024) char sA[16384];   // 128 rows x 128B (64 bf16)
    __shared__ __align__(1024) char sB[16384];

    const int tid  = threadIdx.x;
    const int wid  = tid >> 5;
    const int lane = tid & 31;
    const int warp_m = wid >> 2;          // 0..1  (64 rows each)
    const int warp_n = wid & 3;           // 0..3  (32 cols each)

    const int m0 = blockIdx.x * 128;
    const int n0 = blockIdx.y * 128;

    const uint32_t sbA = smem_u32(sA);
    const uint32_t sbB = smem_u32(sB);

    // gmem->smem mapping: 1024 16B chunks per tile, 4 per thread
    int ldrow[4], ldc8[4];
    uint32_t stoff[4];
#pragma unroll
    for (int t = 0; t < 4; t++) {
        int g = tid + t * 256;
        ldrow[t] = g >> 3;
        ldc8[t]  = g & 7;
        stoff[t] = sw128((uint32_t)(ldrow[t] * 128 + ldc8[t] * 16));
    }

    // ldmatrix source addresses (constant per thread across iterations)
    // A m-tile mt: rows warp_m*64 + mt*16 + (lane&15 in ldmatrix order)
    const int a_r = (lane & 7) + ((lane >> 3) & 1) * 8;     // row within 16
    const int a_c = (lane >> 4) * 16;                       // 0 or 16 bytes
    uint32_t a_addr[4];
#pragma unroll
    for (int mt = 0; mt < 4; mt++) {
        int row = warp_m * 64 + mt * 16 + a_r;
        a_addr[mt] = sbA + sw128((uint32_t)(row * 128 + a_c));
    }
    // B n-tile pair bt (16 n-rows): matrices [n0-7,k0],[n0-7,k16B],[n8-15,k0],[n8-15,k16B]
    const int b_r = ((lane >> 4) & 1) * 8 + (lane & 7);
    const int b_c = ((lane >> 3) & 1) * 16;
    uint32_t b_addr[2];
#pragma unroll
    for (int bt = 0; bt < 2; bt++) {
        int row = warp_n * 32 + bt * 16 + b_r;
        b_addr[bt] = sbB + sw128((uint32_t)(row * 128 + b_c));
    }

    float acc[4][4][4];
#pragma unroll
    for (int i = 0; i < 4; i++)
#pragma unroll
        for (int j = 0; j < 4; j++)
#pragma unroll
            for (int k = 0; k < 4; k++) acc[i][j][k] = 0.f;

    const __nv_bfloat16* Ap[3] = {Ahi, Ahi, Alo};
    const __nv_bfloat16* Bp[3] = {Bhi, Blo, Bhi};

    for (int it = 0; it < 18; it++) {
        const int pass = it / 6;
        const int kc   = (it - pass * 6) * 64;
        const char* Asrc = (const char*)(Ap[pass] + (size_t)m0 * C + kc);
        const char* Bsrc = (const char*)(Bp[pass] + (size_t)n0 * C + kc);

        uint4 va[4], vb[4];
#pragma unroll
        for (int t = 0; t < 4; t++) {
            va[t] = *(const uint4*)(Asrc + (size_t)ldrow[t] * (C * 2) + ldc8[t] * 16);
            vb[t] = *(const uint4*)(Bsrc + (size_t)ldrow[t] * (C * 2) + ldc8[t] * 16);
        }
        __syncthreads();   // previous iteration's compute done
#pragma unroll
        for (int t = 0; t < 4; t++) {
            *(uint4*)(sA + stoff[t]) = va[t];
            *(uint4*)(sB + stoff[t]) = vb[t];
        }
        __syncthreads();

#pragma unroll
        for (int k16 = 0; k16 < 4; k16++) {
            const uint32_t koff = (uint32_t)(k16 * 32);
            // swizzle is XOR in bits [4:6]; adding k16*32 before swizzle ==
            // XOR'ing after only for bit5/bit6 region... recompute properly:
            uint32_t a[4][4], b[4][2];
#pragma unroll
            for (int mt = 0; mt < 4; mt++) {
                int row = warp_m * 64 + mt * 16 + a_r;
                uint32_t ad = sbA + sw128((uint32_t)(row * 128 + koff + a_c));
                ldsm_x4(a[mt][0], a[mt][1], a[mt][2], a[mt][3], ad);
            }
#pragma unroll
            for (int bt = 0; bt < 2; bt++) {
                int row = warp_n * 32 + bt * 16 + b_r;
                uint32_t bd = sbB + sw128((uint32_t)(row * 128 + koff + b_c));
                ldsm_x4(b[bt * 2][0], b[bt * 2][1], b[bt * 2 + 1][0], b[bt * 2 + 1][1], bd);
            }
#pragma unroll
            for (int mt = 0; mt < 4; mt++)
#pragma unroll
                for (int nt = 0; nt < 4; nt++)
                    mma16816(acc[mt][nt], a[mt], b[nt]);
        }
    }

    // Epilogue: D fragment rows/cols + bias
    const int er = lane >> 2;          // 0..7
    const int ec = (lane & 3) * 2;     // 0,2,..6
#pragma unroll
    for (int mt = 0; mt < 4; mt++) {
#pragma unroll
        for (int nt = 0; nt < 4; nt++) {
            int col = n0 + warp_n * 32 + nt * 8 + ec;
            float b0 = bias[col], b1 = bias[col + 1];
            int row0 = m0 + warp_m * 64 + mt * 16 + er;
            float2 v0 = {acc[mt][nt][0] + b0, acc[mt][nt][1] + b1};
            float2 v1 = {acc[mt][nt][2] + b0, acc[mt][nt][3] + b1};
            *(float2*)(out + (size_t)row0 * ldout + col)       = v0;
            *(float2*)(out + (size_t)(row0 + 8) * ldout + col) = v1;
        }
    }
}

// ---------------------------------------------------------------------------
// Attention: per (head, window). Gathers q/k/v from pixel-order g_qkv via the
// shifted-window mapping; writes bf16 hi/lo output in pixel order.
// ---------------------------------------------------------------------------
__global__ __launch_bounds__(128) void attn_kernel(const float* __restrict__ table) {
    const int h    = blockIdx.x;
    const int wwin = blockIdx.y;

    __shared__ float qs[NT * HD];
    __shared__ float kst[HD * 57];      // transposed k, odd stride
    __shared__ float vs[NT * HD];
    __shared__ float s[NT * 53];
    __shared__ float biasTab[169];
    __shared__ int   cnt[NT];
    __shared__ int   pix[NT];

    const int tid = threadIdx.x;
    const float scale = 0.17677669529663687f;   // 32^-0.5

    const int wi = wwin & 63;
    const int iw = wi >> 3, jw = wi & 7;
    if (tid < NT) {
        int r = tid / WS, c = tid - (tid / WS) * WS;
        int hh = iw * WS + r + SHF; if (hh >= IMG) hh -= IMG;
        int ww = jw * WS + c + SHF; if (ww >= IMG) ww -= IMG;
        pix[tid] = ((wwin >> 6) * IMG + hh) * IMG + ww;
        int ch = (iw < NWIN1 - 1) ? 0 : (r < WS - SHF ? 1 : 2);
        int cw = (jw < NWIN1 - 1) ? 0 : (c < WS - SHF ? 1 : 2);
        cnt[tid] = ch * 3 + cw;
    }
    for (int e = tid; e < 169; e += 128) biasTab[e] = table[e * NH + h];
    __syncthreads();

    for (int e = tid; e < NT * HD; e += 128) {
        int i = e >> 5, d = e & 31;
        const float* row = g_qkv + (size_t)pix[i] * NQKV + h * HD + d;
        qs[e]           = row[0] * scale;
        kst[d * 57 + i] = row[C];
        vs[e]           = row[2 * C];
    }
    __syncthreads();

    for (int p = tid; p < NT * NT; p += 128) {
        int i = p / NT, j = p - i * NT;
        float acc = 0.f;
#pragma unroll
        for (int d = 0; d < HD; d++) acc += qs[i * HD + d] * kst[d * 57 + j];
        int r1 = i / WS, c1 = i - r1 * WS;
        int r2 = j / WS, c2 = j - r2 * WS;
        acc += biasTab[(r1 - r2 + WS - 1) * (2 * WS - 1) + (c1 - c2 + WS - 1)];
        if (cnt[i] != cnt[j]) acc -= 100.f;
        s[i * 53 + j] = acc;
    }
    __syncthreads();

    if (tid < NT) {
        float mx = -1e30f;
#pragma unroll 7
        for (int j = 0; j < NT; j++) mx = fmaxf(mx, s[tid * 53 + j]);
        float sum = 0.f;
#pragma unroll 7
        for (int j = 0; j < NT; j++) {
            float e = __expf(s[tid * 53 + j] - mx);
            s[tid * 53 + j] = e; sum += e;
        }
        float inv = 1.f / sum;
#pragma unroll 7
        for (int j = 0; j < NT; j++) s[tid * 53 + j] *= inv;
    }
    __syncthreads();

    for (int o = tid; o < NT * HD; o += 128) {
        int i = o >> 5, d = o & 31;
        float acc = 0.f;
#pragma unroll 7
        for (int j = 0; j < NT; j++) acc += s[i * 53 + j] * vs[j * HD + d];
        size_t off = (size_t)pix[i] * C + h * HD + d;
        __nv_bfloat16 hv = __float2bfloat16(acc);
        g_ahi[off] = hv;
        g_alo[off] = __float2bfloat16(acc - __bfloat162float(hv));
    }
}

// ---------------------------------------------------------------------------
extern "C" void kernel_launch(void* const* d_in, const int* in_sizes, int n_in,
                              void* d_out, int out_size) {
    const float* x     = (const float*)d_in[0];
    const float* qkvw  = (const float*)d_in[1];
    const float* qkvb  = (const float*)d_in[2];
    const float* projw = (const float*)d_in[3];
    const float* projb = (const float*)d_in[4];
    const float* table = (const float*)d_in[5];
    float* out = (float*)d_out;

    void *p_qkv, *p_xhi, *p_xlo, *p_ahi, *p_alo, *p_wqh, *p_wql, *p_wph, *p_wpl;
    cudaGetSymbolAddress(&p_qkv, g_qkv);
    cudaGetSymbolAddress(&p_xhi, g_xhi);  cudaGetSymbolAddress(&p_xlo, g_xlo);
    cudaGetSymbolAddress(&p_ahi, g_ahi);  cudaGetSymbolAddress(&p_alo, g_alo);
    cudaGetSymbolAddress(&p_wqh, g_wqh);  cudaGetSymbolAddress(&p_wql, g_wql);
    cudaGetSymbolAddress(&p_wph, g_wph);  cudaGetSymbolAddress(&p_wpl, g_wpl);

    // bf16 hi/lo splits
    int n4x = (MROWS * C) / 4;
    conv_split4<<<(n4x + 255) / 256, 256>>>((const float4*)x,
        (__nv_bfloat16*)p_xhi, (__nv_bfloat16*)p_xlo, n4x);
    int n4q = (NQKV * C) / 4;
    conv_split4<<<(n4q + 255) / 256, 256>>>((const float4*)qkvw,
        (__nv_bfloat16*)p_wqh, (__nv_bfloat16*)p_wql, n4q);
    int n4p = (C * C) / 4;
    conv_split4<<<(n4p + 255) / 256, 256>>>((const float4*)projw,
        (__nv_bfloat16*)p_wph, (__nv_bfloat16*)p_wpl, n4p);

    // QKV GEMM: [50176 x 384] @ [1152 x 384]^T -> g_qkv (pixel order)
    mma_gemm<<<dim3(MROWS / 128, NQKV / 128), 256>>>(
        (const __nv_bfloat16*)p_xhi, (const __nv_bfloat16*)p_xlo,
        (const __nv_bfloat16*)p_wqh, (const __nv_bfloat16*)p_wql,
        qkvb, (float*)p_qkv, NQKV);

    // Attention per (head, window)
    attn_kernel<<<dim3(NH, NWTOT), 128>>>(table);

    // Proj GEMM: [50176 x 384] @ [384 x 384]^T -> out
    mma_gemm<<<dim3(MROWS / 128, C / 128), 256>>>(
        (const __nv_bfloat16*)p_ahi, (const __nv_bfloat16*)p_alo,
        (const __nv_bfloat16*)p_wph, (const __nv_bfloat16*)p_wpl,
        projb, out, C);
}

// round 5
// speedup vs baseline: 3.5978x; 1.7212x over previous
#include <cuda_runtime.h>
#include <cuda_bf16.h>
#include <cstdint>

// ---------------------------------------------------------------------------
// Problem constants (B=16, 56x56x384, 12 heads, 7x7 windows, shift 3)
// ---------------------------------------------------------------------------
constexpr int IMG   = 56;
constexpr int C     = 384;
constexpr int NH    = 12;
constexpr int HD    = 32;
constexpr int WS    = 7;
constexpr int SHF   = 3;
constexpr int NWIN1 = 8;
constexpr int NT    = WS * WS;            // 49
constexpr int NWTOT = 16 * 64;            // 1024 windows
constexpr int MROWS = 16 * IMG * IMG;     // 50176
constexpr int NQKV  = 3 * C;              // 1152

// ---------------------------------------------------------------------------
// Device-global scratch (no runtime allocation allowed)
// ---------------------------------------------------------------------------
__device__ float          g_qkv[(size_t)MROWS * NQKV];
__device__ __nv_bfloat16  g_xhi[(size_t)MROWS * C];
__device__ __nv_bfloat16  g_xlo[(size_t)MROWS * C];
__device__ __nv_bfloat16  g_ahi[(size_t)MROWS * C];
__device__ __nv_bfloat16  g_alo[(size_t)MROWS * C];
__device__ __nv_bfloat16  g_wqh[(size_t)NQKV * C];
__device__ __nv_bfloat16  g_wql[(size_t)NQKV * C];
__device__ __nv_bfloat16  g_wph[(size_t)C * C];
__device__ __nv_bfloat16  g_wpl[(size_t)C * C];

// ---------------------------------------------------------------------------
// Portable PTX helpers (sm_80-level, valid for compute_103)
// ---------------------------------------------------------------------------
__device__ __forceinline__ uint32_t smem_u32(const void* p) {
    uint32_t a;
    asm("{ .reg .u64 t; cvta.to.shared.u64 t, %1; cvt.u32.u64 %0, t; }"
        : "=r"(a) : "l"(p));
    return a;
}
__device__ __forceinline__ void ldsm_x4(uint32_t& r0, uint32_t& r1,
                                        uint32_t& r2, uint32_t& r3, uint32_t addr) {
    asm volatile("ldmatrix.sync.aligned.m8n8.x4.shared.b16 {%0,%1,%2,%3}, [%4];"
                 : "=r"(r0), "=r"(r1), "=r"(r2), "=r"(r3) : "r"(addr));
}
__device__ __forceinline__ void mma16816(float* d, const uint32_t* a, const uint32_t* b) {
    asm volatile(
        "mma.sync.aligned.m16n8k16.row.col.f32.bf16.bf16.f32 "
        "{%0,%1,%2,%3}, {%4,%5,%6,%7}, {%8,%9}, {%0,%1,%2,%3};"
        : "+f"(d[0]), "+f"(d[1]), "+f"(d[2]), "+f"(d[3])
        : "r"(a[0]), "r"(a[1]), "r"(a[2]), "r"(a[3]), "r"(b[0]), "r"(b[1]));
}
#define CP_ASYNC16(dst, src) \
    asm volatile("cp.async.cg.shared.global [%0], [%1], 16;" :: "r"(dst), "l"(src))
#define CP_COMMIT()  asm volatile("cp.async.commit_group;")
#define CP_WAIT(N)   asm volatile("cp.async.wait_group %0;" :: "n"(N))

// SW64 swizzle for 64-byte rows
__device__ __forceinline__ uint32_t sw64(uint32_t o) { return o ^ ((o >> 3) & 0x30); }

// ---------------------------------------------------------------------------
// fp32 -> bf16 hi/lo split (x = hi + lo)
// ---------------------------------------------------------------------------
__global__ void conv_split4(const float4* __restrict__ src,
                            __nv_bfloat16* __restrict__ hi,
                            __nv_bfloat16* __restrict__ lo, int n4) {
    int i = blockIdx.x * blockDim.x + threadIdx.x;
    if (i >= n4) return;
    float4 v = src[i];
    float vv[4] = {v.x, v.y, v.z, v.w};
    __nv_bfloat16 h[4], l[4];
#pragma unroll
    for (int j = 0; j < 4; j++) {
        h[j] = __float2bfloat16(vv[j]);
        l[j] = __float2bfloat16(vv[j] - __bfloat162float(h[j]));
    }
    __nv_bfloat162* hp = (__nv_bfloat162*)(hi + (size_t)i * 4);
    __nv_bfloat162* lp = (__nv_bfloat162*)(lo + (size_t)i * 4);
    hp[0] = __nv_bfloat162(h[0], h[1]); hp[1] = __nv_bfloat162(h[2], h[3]);
    lp[0] = __nv_bfloat162(l[0], l[1]); lp[1] = __nv_bfloat162(l[2], l[3]);
}

// ---------------------------------------------------------------------------
// HMMA GEMM: out = (Ahi+Alo) @ (Bhi+Blo)^T + bias, 3 product passes per
// k-chunk. CTA tile 128x128, BK=32, cp.async double-buffered, 8 warps,
// warp tile 64x32. grid=(M/128, N/128), 256 threads.
// Stage layout: [Ahi 8K][Alo 8K][Bhi 8K][Blo 8K] = 32KB, two stages = 64KB.
// ---------------------------------------------------------------------------
constexpr int STG = 32768;
constexpr int NCH = C / 32;   // 12

__global__ __launch_bounds__(256) void mma_gemm(
    const __nv_bfloat16* __restrict__ Ahi, const __nv_bfloat16* __restrict__ Alo,
    const __nv_bfloat16* __restrict__ Bhi, const __nv_bfloat16* __restrict__ Blo,
    const float* __restrict__ bias, float* __restrict__ out, int ldout) {

    extern __shared__ __align__(128) char smem[];
    const uint32_t sb = smem_u32(smem);

    const int tid  = threadIdx.x;
    const int wid  = tid >> 5;
    const int lane = tid & 31;
    const int warp_m = wid >> 2;
    const int warp_n = wid & 3;

    const int m0 = blockIdx.x * 128;
    const int n0 = blockIdx.y * 128;

    // per-thread cp.async mapping: tile is 128 rows x 64B = 512 16B units
    const int u0   = tid;              // unit 0
    const int u1   = tid + 256;        // unit 1
    const int r0_  = u0 >> 2, c0_ = (u0 & 3) * 16;
    const int r1_  = u1 >> 2, c1_ = (u1 & 3) * 16;
    const uint32_t st0 = sw64((uint32_t)(r0_ * 64 + c0_));
    const uint32_t st1 = sw64((uint32_t)(r1_ * 64 + c1_));

    const char* srcA[2] = {(const char*)(Ahi + (size_t)m0 * C),
                           (const char*)(Alo + (size_t)m0 * C)};
    const char* srcB[2] = {(const char*)(Bhi + (size_t)n0 * C),
                           (const char*)(Blo + (size_t)n0 * C)};

    auto issue_stage = [&](int ch, int buf) {
        const int kb = ch * 64;                 // byte offset of chunk in a row
        const uint32_t base = sb + buf * STG;
#pragma unroll
        for (int t = 0; t < 2; t++) {
            const char* a = srcA[t];
            const char* b = srcB[t];
            CP_ASYNC16(base + t * 8192 + st0,         a + (size_t)r0_ * (C * 2) + kb + c0_);
            CP_ASYNC16(base + t * 8192 + st1,         a + (size_t)r1_ * (C * 2) + kb + c1_);
            CP_ASYNC16(base + 16384 + t * 8192 + st0, b + (size_t)r0_ * (C * 2) + kb + c0_);
            CP_ASYNC16(base + 16384 + t * 8192 + st1, b + (size_t)r1_ * (C * 2) + kb + c1_);
        }
    };

    // ldmatrix lane geometry
    const int a_r = (lane & 7) + ((lane >> 3) & 1) * 8;
    const int a_c = (lane >> 4) * 16;
    const int b_r = ((lane >> 4) & 1) * 8 + (lane & 7);
    const int b_c = ((lane >> 3) & 1) * 16;

    float acc[4][4][4];
#pragma unroll
    for (int i = 0; i < 4; i++)
#pragma unroll
        for (int j = 0; j < 4; j++)
#pragma unroll
            for (int k = 0; k < 4; k++) acc[i][j][k] = 0.f;

    issue_stage(0, 0);
    CP_COMMIT();

    for (int ch = 0; ch < NCH; ch++) {
        const int buf = ch & 1;
        if (ch + 1 < NCH) {
            issue_stage(ch + 1, buf ^ 1);
            CP_COMMIT();
            CP_WAIT(1);
        } else {
            CP_WAIT(0);
        }
        __syncthreads();

        const uint32_t base = sb + buf * STG;
#pragma unroll
        for (int k16 = 0; k16 < 2; k16++) {
            const uint32_t kb = (uint32_t)(k16 * 32);
            uint32_t ah[4][4], al[4][4], bh[4][2], bl[4][2];
#pragma unroll
            for (int mt = 0; mt < 4; mt++) {
                int row = warp_m * 64 + mt * 16 + a_r;
                uint32_t so = sw64((uint32_t)(row * 64 + kb + a_c));
                ldsm_x4(ah[mt][0], ah[mt][1], ah[mt][2], ah[mt][3], base + so);
                ldsm_x4(al[mt][0], al[mt][1], al[mt][2], al[mt][3], base + 8192 + so);
            }
#pragma unroll
            for (int bt = 0; bt < 2; bt++) {
                int row = warp_n * 32 + bt * 16 + b_r;
                uint32_t so = sw64((uint32_t)(row * 64 + kb + b_c));
                ldsm_x4(bh[bt*2][0], bh[bt*2][1], bh[bt*2+1][0], bh[bt*2+1][1],
                        base + 16384 + so);
                ldsm_x4(bl[bt*2][0], bl[bt*2][1], bl[bt*2+1][0], bl[bt*2+1][1],
                        base + 24576 + so);
            }
#pragma unroll
            for (int mt = 0; mt < 4; mt++)
#pragma unroll
                for (int nt = 0; nt < 4; nt++) {
                    mma16816(acc[mt][nt], ah[mt], bh[nt]);
                    mma16816(acc[mt][nt], ah[mt], bl[nt]);
                    mma16816(acc[mt][nt], al[mt], bh[nt]);
                }
        }
        __syncthreads();
    }

    // Epilogue: D fragments + bias
    const int er = lane >> 2;
    const int ec = (lane & 3) * 2;
#pragma unroll
    for (int mt = 0; mt < 4; mt++) {
#pragma unroll
        for (int nt = 0; nt < 4; nt++) {
            int col = n0 + warp_n * 32 + nt * 8 + ec;
            float b0 = bias[col], b1 = bias[col + 1];
            int row0 = m0 + warp_m * 64 + mt * 16 + er;
            float2 v0 = {acc[mt][nt][0] + b0, acc[mt][nt][1] + b1};
            float2 v1 = {acc[mt][nt][2] + b0, acc[mt][nt][3] + b1};
            *(float2*)(out + (size_t)row0 * ldout + col)       = v0;
            *(float2*)(out + (size_t)(row0 + 8) * ldout + col) = v1;
        }
    }
}

// ---------------------------------------------------------------------------
// Attention per (head, window). q_i register-resident for scores; P@V
// register-accumulated. All fp32 in smem (accuracy), bf16 hi/lo out.
// ---------------------------------------------------------------------------
__global__ __launch_bounds__(128) void attn_kernel(const float* __restrict__ table) {
    const int h    = blockIdx.x;
    const int wwin = blockIdx.y;

    __shared__ float qs[NT * HD];
    __shared__ float kk[NT * HD];
    __shared__ float vv[NT * HD];
    __shared__ float s[NT * 53];
    __shared__ float biasTab[169];
    __shared__ int   cnt[NT];
    __shared__ int   pix[NT];

    const int tid = threadIdx.x;
    const float scale = 0.17677669529663687f;   // 32^-0.5

    const int wi = wwin & 63;
    const int iw = wi >> 3, jw = wi & 7;
    if (tid < NT) {
        int r = tid / WS, c = tid - (tid / WS) * WS;
        int hh = iw * WS + r + SHF; if (hh >= IMG) hh -= IMG;
        int ww = jw * WS + c + SHF; if (ww >= IMG) ww -= IMG;
        pix[tid] = ((wwin >> 6) * IMG + hh) * IMG + ww;
        int ch = (iw < NWIN1 - 1) ? 0 : (r < WS - SHF ? 1 : 2);
        int cw = (jw < NWIN1 - 1) ? 0 : (c < WS - SHF ? 1 : 2);
        cnt[tid] = ch * 3 + cw;
    }
    for (int e = tid; e < 169; e += 128) biasTab[e] = table[e * NH + h];
    __syncthreads();

    for (int e = tid; e < NT * HD; e += 128) {
        int i = e >> 5, d = e & 31;
        const float* row = g_qkv + (size_t)pix[i] * NQKV + h * HD + d;
        qs[e] = row[0] * scale;
        kk[e] = row[C];
        vv[e] = row[2 * C];
    }
    __syncthreads();

    // Scores: thread = (i, j-half). q_i in registers; K rows broadcast.
    if (tid < 2 * NT) {
        const int i  = tid >> 1;
        const int jh = tid & 1;
        float q[32];
#pragma unroll
        for (int d4 = 0; d4 < 8; d4++) {
            float4 v = *(const float4*)(qs + i * HD + d4 * 4);
            q[d4*4+0] = v.x; q[d4*4+1] = v.y; q[d4*4+2] = v.z; q[d4*4+3] = v.w;
        }
        const int r1 = i / WS, c1 = i - r1 * WS;
        const int ci = cnt[i];
        const int j0 = jh * 25, j1 = jh ? NT : 25;
        for (int j = j0; j < j1; j++) {
            float acc = 0.f;
#pragma unroll
            for (int d4 = 0; d4 < 8; d4++) {
                float4 kv = *(const float4*)(kk + j * HD + d4 * 4);
                acc += q[d4*4+0] * kv.x + q[d4*4+1] * kv.y
                     + q[d4*4+2] * kv.z + q[d4*4+3] * kv.w;
            }
            int r2 = j / WS, c2 = j - r2 * WS;
            acc += biasTab[(r1 - r2 + WS - 1) * (2 * WS - 1) + (c1 - c2 + WS - 1)];
            if (ci != cnt[j]) acc -= 100.f;
            s[i * 53 + j] = acc;
        }
    }
    __syncthreads();

    // Softmax per row
    if (tid < NT) {
        float mx = -1e30f;
#pragma unroll 7
        for (int j = 0; j < NT; j++) mx = fmaxf(mx, s[tid * 53 + j]);
        float sum = 0.f;
#pragma unroll 7
        for (int j = 0; j < NT; j++) {
            float e = __expf(s[tid * 53 + j] - mx);
            s[tid * 53 + j] = e; sum += e;
        }
        float inv = 1.f / sum;
#pragma unroll 7
        for (int j = 0; j < NT; j++) s[tid * 53 + j] *= inv;
    }
    __syncthreads();

    // P@V: thread = (i, d-half of 16). Register accumulators.
    if (tid < 2 * NT) {
        const int i  = tid >> 1;
        const int dh = (tid & 1) * 16;
        float acc[16];
#pragma unroll
        for (int k = 0; k < 16; k++) acc[k] = 0.f;
        for (int j = 0; j < NT; j++) {
            float pj = s[i * 53 + j];
#pragma unroll
            for (int d4 = 0; d4 < 4; d4++) {
                float4 v = *(const float4*)(vv + j * HD + dh + d4 * 4);
                acc[d4*4+0] += pj * v.x; acc[d4*4+1] += pj * v.y;
                acc[d4*4+2] += pj * v.z; acc[d4*4+3] += pj * v.w;
            }
        }
        size_t off = (size_t)pix[i] * C + h * HD + dh;
        __nv_bfloat162* oh = (__nv_bfloat162*)(g_ahi + off);
        __nv_bfloat162* ol = (__nv_bfloat162*)(g_alo + off);
#pragma unroll
        for (int k = 0; k < 8; k++) {
            float a0 = acc[2*k], a1 = acc[2*k+1];
            __nv_bfloat16 h0 = __float2bfloat16(a0);
            __nv_bfloat16 h1 = __float2bfloat16(a1);
            oh[k] = __nv_bfloat162(h0, h1);
            ol[k] = __nv_bfloat162(__float2bfloat16(a0 - __bfloat162float(h0)),
                                   __float2bfloat16(a1 - __bfloat162float(h1)));
        }
    }
}

// ---------------------------------------------------------------------------
extern "C" void kernel_launch(void* const* d_in, const int* in_sizes, int n_in,
                              void* d_out, int out_size) {
    const float* x     = (const float*)d_in[0];
    const float* qkvw  = (const float*)d_in[1];
    const float* qkvb  = (const float*)d_in[2];
    const float* projw = (const float*)d_in[3];
    const float* projb = (const float*)d_in[4];
    const float* table = (const float*)d_in[5];
    float* out = (float*)d_out;

    void *p_qkv, *p_xhi, *p_xlo, *p_ahi, *p_alo, *p_wqh, *p_wql, *p_wph, *p_wpl;
    cudaGetSymbolAddress(&p_qkv, g_qkv);
    cudaGetSymbolAddress(&p_xhi, g_xhi);  cudaGetSymbolAddress(&p_xlo, g_xlo);
    cudaGetSymbolAddress(&p_ahi, g_ahi);  cudaGetSymbolAddress(&p_alo, g_alo);
    cudaGetSymbolAddress(&p_wqh, g_wqh);  cudaGetSymbolAddress(&p_wql, g_wql);
    cudaGetSymbolAddress(&p_wph, g_wph);  cudaGetSymbolAddress(&p_wpl, g_wpl);

    cudaFuncSetAttribute(mma_gemm, cudaFuncAttributeMaxDynamicSharedMemorySize, 2 * STG);

    int n4x = (MROWS * C) / 4;
    conv_split4<<<(n4x + 255) / 256, 256>>>((const float4*)x,
        (__nv_bfloat16*)p_xhi, (__nv_bfloat16*)p_xlo, n4x);
    int n4q = (NQKV * C) / 4;
    conv_split4<<<(n4q + 255) / 256, 256>>>((const float4*)qkvw,
        (__nv_bfloat16*)p_wqh, (__nv_bfloat16*)p_wql, n4q);
    int n4p = (C * C) / 4;
    conv_split4<<<(n4p + 255) / 256, 256>>>((const float4*)projw,
        (__nv_bfloat16*)p_wph, (__nv_bfloat16*)p_wpl, n4p);

    mma_gemm<<<dim3(MROWS / 128, NQKV / 128), 256, 2 * STG>>>(
        (const __nv_bfloat16*)p_xhi, (const __nv_bfloat16*)p_xlo,
        (const __nv_bfloat16*)p_wqh, (const __nv_bfloat16*)p_wql,
        qkvb, (float*)p_qkv, NQKV);

    attn_kernel<<<dim3(NH, NWTOT), 128>>>(table);

    mma_gemm<<<dim3(MROWS / 128, C / 128), 256, 2 * STG>>>(
        (const __nv_bfloat16*)p_ahi, (const __nv_bfloat16*)p_alo,
        (const __nv_bfloat16*)p_wph, (const __nv_bfloat16*)p_wpl,
        projb, out, C);
}